// round 6
// baseline (speedup 1.0000x reference)
#include <cuda_runtime.h>
#include <math.h>

// Problem constants
#define BB   2
#define SS   2048
#define DD   2048
#define HQN  16
#define DHH  128
#define MR   (BB*SS)          // 4096 rows for all GEMMs

// -------- scratch (no allocation allowed -> __device__ globals) --------
__device__ float g_Q [MR * DD];   // 32 MB : Q projection, [b*s, h*dh]
__device__ float g_K [MR * DHH];  //  2 MB : shared K head, [b*s, dh]
__device__ float g_V [MR * DHH];  //  2 MB
__device__ float g_AO[MR * DD];   // 32 MB : attention output, [b*s, h*dh]

// ============================================================================
// SGEMM: C[M,N] = A[M,K] @ W[K,N] + bias[N]
// BM=BN=128, BK=16, 256 threads, 8x8 per thread (4+4 split tiles).
// M,N,K assumed multiples of 128/128/16 (true here: M=4096, N in {128,2048}, K=2048).
// ============================================================================
__global__ __launch_bounds__(256)
void sgemm_bias(const float* __restrict__ A, const float* __restrict__ W,
                const float* __restrict__ bias, float* __restrict__ C,
                int M, int N, int K)
{
    __shared__ float As[16][132];   // As[k][m], padded to kill store conflicts
    __shared__ float Bs[16][132];   // Bs[k][n]

    const int tid = threadIdx.x;
    const int tx  = tid & 15;       // 0..15 -> N direction
    const int ty  = tid >> 4;       // 0..15 -> M direction
    const int bx  = blockIdx.x;     // N tile
    const int by  = blockIdx.y;     // M tile

    float acc[8][8];
#pragma unroll
    for (int i = 0; i < 8; i++)
#pragma unroll
        for (int j = 0; j < 8; j++) acc[i][j] = 0.f;

    const float* Ab = A + (size_t)(by * 128) * K;
    const float* Wb = W + bx * 128;

    for (int kt = 0; kt < K; kt += 16) {
        // cooperative loads: 128x16 A tile (transposed into As), 16x128 W tile
#pragma unroll
        for (int i = 0; i < 2; i++) {
            int li = tid + i * 256;                   // 0..511 (float4 index)
            int ar = li >> 2, ac = (li & 3) << 2;     // A: row 0..127, col {0,4,8,12}
            float4 av = *(const float4*)(Ab + (size_t)ar * K + kt + ac);
            As[ac + 0][ar] = av.x;
            As[ac + 1][ar] = av.y;
            As[ac + 2][ar] = av.z;
            As[ac + 3][ar] = av.w;
            int br = li >> 5, bc = (li & 31) << 2;    // W: row 0..15, col {0..124}
            *(float4*)&Bs[br][bc] = *(const float4*)(Wb + (size_t)(kt + br) * N + bc);
        }
        __syncthreads();

#pragma unroll 8
        for (int k = 0; k < 16; k++) {
            float a[8], b[8];
            *(float4*)&a[0] = *(const float4*)&As[k][ty * 4];
            *(float4*)&a[4] = *(const float4*)&As[k][64 + ty * 4];
            *(float4*)&b[0] = *(const float4*)&Bs[k][tx * 4];
            *(float4*)&b[4] = *(const float4*)&Bs[k][64 + tx * 4];
#pragma unroll
            for (int i = 0; i < 8; i++)
#pragma unroll
                for (int j = 0; j < 8; j++)
                    acc[i][j] = fmaf(a[i], b[j], acc[i][j]);
        }
        __syncthreads();
    }

    // epilogue: + bias, vectorized stores
#pragma unroll
    for (int i = 0; i < 8; i++) {
        int r = (i < 4) ? (ty * 4 + i) : (64 + ty * 4 + (i - 4));
        size_t rowoff = (size_t)(by * 128 + r) * N + bx * 128;
#pragma unroll
        for (int jh = 0; jh < 2; jh++) {
            int c = jh ? (64 + tx * 4) : (tx * 4);
            float4 bv = *(const float4*)(bias + bx * 128 + c);
            float4 o;
            o.x = acc[i][jh * 4 + 0] + bv.x;
            o.y = acc[i][jh * 4 + 1] + bv.y;
            o.z = acc[i][jh * 4 + 2] + bv.z;
            o.w = acc[i][jh * 4 + 3] + bv.w;
            *(float4*)(C + rowoff + c) = o;
        }
    }
}

// ============================================================================
// Flash attention (fp32), one block per (b, h, 64-query tile).
// 256 threads: tx = tid&15 (key/col dir), ty = tid>>4 (query/row dir).
// Each thread: 4 query rows x {4 score cols | 8 output cols}.
// Online softmax with running (m, l). Q pre-scaled by 1/sqrt(DH).
// ============================================================================
#define FBM   64
#define FBN   64
#define QSTR  132                   // padded row stride (floats) for Q/K/V tiles
#define PSTR  65                    // padded row stride for P tile
#define OFF_K (FBM * QSTR)
#define OFF_V (OFF_K + FBN * QSTR)
#define OFF_P (OFF_V + FBN * QSTR)
#define FLASH_SMEM_FLOATS (OFF_P + FBM * PSTR)
#define FLASH_SMEM_BYTES  (FLASH_SMEM_FLOATS * 4)   // 118016 B

__global__ __launch_bounds__(256, 1)
void flash_kernel(const float* __restrict__ Qg, const float* __restrict__ Kg,
                  const float* __restrict__ Vg, float* __restrict__ Og)
{
    extern __shared__ float sm[];
    float* Qs = sm;
    float* Ks = sm + OFF_K;
    float* Vs = sm + OFF_V;
    float* Ps = sm + OFF_P;

    const int tid = threadIdx.x;
    const int tx  = tid & 15;
    const int ty  = tid >> 4;
    const int q0  = blockIdx.x * FBM;
    const int b   = blockIdx.y / HQN;
    const int h   = blockIdx.y % HQN;
    const float scale = 0.088388347648318447f;  // 1/sqrt(128)

    // ---- load + pre-scale Q tile [64 x 128] ----
    const float* Qbase = Qg + ((size_t)(b * SS + q0)) * DD + h * DHH;
    for (int li = tid; li < FBM * 32; li += 256) {
        int r = li >> 5, c4 = (li & 31) << 2;
        float4 v = *(const float4*)(Qbase + (size_t)r * DD + c4);
        v.x *= scale; v.y *= scale; v.z *= scale; v.w *= scale;
        *(float4*)&Qs[r * QSTR + c4] = v;
    }

    float acc[4][8];
    float m[4], l[4];
#pragma unroll
    for (int i = 0; i < 4; i++) {
        m[i] = -1e30f; l[i] = 0.f;
#pragma unroll
        for (int j = 0; j < 8; j++) acc[i][j] = 0.f;
    }

    const float* Kb = Kg + (size_t)b * SS * DHH;
    const float* Vb = Vg + (size_t)b * SS * DHH;

    for (int t0 = 0; t0 < SS; t0 += FBN) {
        // ---- load K, V tiles [64 x 128] ----
        for (int li = tid; li < FBN * 32; li += 256) {
            int r = li >> 5, c4 = (li & 31) << 2;
            *(float4*)&Ks[r * QSTR + c4] = *(const float4*)(Kb + (size_t)(t0 + r) * DHH + c4);
            *(float4*)&Vs[r * QSTR + c4] = *(const float4*)(Vb + (size_t)(t0 + r) * DHH + c4);
        }
        __syncthreads();   // also covers Q on the first iteration

        // ---- S = Q . K^T : thread (ty,tx) -> rows ty*4+i, cols tx+16*j ----
        float s[4][4];
#pragma unroll
        for (int i = 0; i < 4; i++)
#pragma unroll
            for (int j = 0; j < 4; j++) s[i][j] = 0.f;

#pragma unroll 4
        for (int d = 0; d < DHH; d += 4) {
            float4 q[4], k[4];
#pragma unroll
            for (int i = 0; i < 4; i++)
                q[i] = *(const float4*)&Qs[(ty * 4 + i) * QSTR + d];
#pragma unroll
            for (int j = 0; j < 4; j++)
                k[j] = *(const float4*)&Ks[(tx + 16 * j) * QSTR + d];
#pragma unroll
            for (int i = 0; i < 4; i++)
#pragma unroll
                for (int j = 0; j < 4; j++) {
                    s[i][j] = fmaf(q[i].x, k[j].x, s[i][j]);
                    s[i][j] = fmaf(q[i].y, k[j].y, s[i][j]);
                    s[i][j] = fmaf(q[i].z, k[j].z, s[i][j]);
                    s[i][j] = fmaf(q[i].w, k[j].w, s[i][j]);
                }
        }

        // ---- online softmax (row groups of 16 lanes; xor<=8 stays in-group) ----
#pragma unroll
        for (int i = 0; i < 4; i++) {
            float lm = fmaxf(fmaxf(s[i][0], s[i][1]), fmaxf(s[i][2], s[i][3]));
#pragma unroll
            for (int off = 8; off >= 1; off >>= 1)
                lm = fmaxf(lm, __shfl_xor_sync(0xffffffffu, lm, off));
            float nm   = fmaxf(m[i], lm);
            float corr = __expf(m[i] - nm);
            float rs = 0.f;
#pragma unroll
            for (int j = 0; j < 4; j++) {
                float p = __expf(s[i][j] - nm);
                s[i][j] = p;
                rs += p;
            }
#pragma unroll
            for (int off = 8; off >= 1; off >>= 1)
                rs += __shfl_xor_sync(0xffffffffu, rs, off);
            l[i] = l[i] * corr + rs;
            m[i] = nm;
#pragma unroll
            for (int j = 0; j < 8; j++) acc[i][j] *= corr;
#pragma unroll
            for (int j = 0; j < 4; j++)
                Ps[(ty * 4 + i) * PSTR + tx + 16 * j] = s[i][j];
        }
        __syncthreads();

        // ---- acc += P . V : thread -> rows ty*4+i, out cols tx+16*jj ----
#pragma unroll 8
        for (int kk = 0; kk < FBN; kk++) {
            float v[8];
#pragma unroll
            for (int jj = 0; jj < 8; jj++) v[jj] = Vs[kk * QSTR + tx + 16 * jj];
#pragma unroll
            for (int i = 0; i < 4; i++) {
                float p = Ps[(ty * 4 + i) * PSTR + kk];
#pragma unroll
                for (int jj = 0; jj < 8; jj++)
                    acc[i][jj] = fmaf(p, v[jj], acc[i][jj]);
            }
        }
        __syncthreads();
    }

    // ---- epilogue: normalize and write to [b*s, h*dh] layout ----
#pragma unroll
    for (int i = 0; i < 4; i++) {
        float inv = 1.f / l[i];
        size_t rowoff = ((size_t)(b * SS + q0 + ty * 4 + i)) * DD + h * DHH;
#pragma unroll
        for (int jj = 0; jj < 8; jj++)
            Og[rowoff + tx + 16 * jj] = acc[i][jj] * inv;
    }
}

// ============================================================================
// Launch
// ============================================================================
extern "C" void kernel_launch(void* const* d_in, const int* in_sizes, int n_in,
                              void* d_out, int out_size)
{
    (void)in_sizes; (void)n_in; (void)out_size;
    const float* x  = (const float*)d_in[0];
    const float* Wq = (const float*)d_in[1];
    const float* bq = (const float*)d_in[2];
    const float* Wk = (const float*)d_in[3];
    const float* bk = (const float*)d_in[4];
    const float* Wv = (const float*)d_in[5];
    const float* bv = (const float*)d_in[6];
    const float* Wo = (const float*)d_in[7];
    const float* bo = (const float*)d_in[8];
    float* out = (float*)d_out;

    void *pQ, *pK, *pV, *pAO;
    cudaGetSymbolAddress(&pQ,  g_Q);
    cudaGetSymbolAddress(&pK,  g_K);
    cudaGetSymbolAddress(&pV,  g_V);
    cudaGetSymbolAddress(&pAO, g_AO);

    cudaFuncSetAttribute(flash_kernel,
                         cudaFuncAttributeMaxDynamicSharedMemorySize,
                         FLASH_SMEM_BYTES);

    dim3 blk(256);

    // 1) Q = x @ Wq + bq        [4096, 2048]
    sgemm_bias<<<dim3(DD / 128, MR / 128), blk>>>(x, Wq, bq, (float*)pQ, MR, DD, DD);
    // 2) K = x @ Wk + bk        [4096, 128]
    sgemm_bias<<<dim3(1, MR / 128), blk>>>(x, Wk, bk, (float*)pK, MR, DHH, DD);
    // 3) V = x @ Wv + bv        [4096, 128]
    sgemm_bias<<<dim3(1, MR / 128), blk>>>(x, Wv, bv, (float*)pV, MR, DHH, DD);
    // 4) attention -> g_AO      [4096, 2048]
    flash_kernel<<<dim3(SS / FBM, BB * HQN), blk, FLASH_SMEM_BYTES>>>(
        (const float*)pQ, (const float*)pK, (const float*)pV, (float*)pAO);
    // 5) out = AO @ Wo + bo     [4096, 2048]
    sgemm_bias<<<dim3(DD / 128, MR / 128), blk>>>((const float*)pAO, Wo, bo, out, MR, DD, DD);
}

// round 7
// speedup vs baseline: 2.2364x; 2.2364x over previous
#include <cuda_runtime.h>
#include <cuda_bf16.h>

// ---------------- problem constants ----------------
#define MTOK  4096          // B*S tokens
#define DMOD  2048
#define NH    16
#define DH    128
#define SEQ   2048
#define NB    2
#define QSCALE 0.08838834764831845f   // 1/sqrt(128)

typedef unsigned int u32;
typedef __nv_bfloat16  bf16;
typedef __nv_bfloat162 bf162;

// ---------------- scratch (device globals; no allocation allowed) --------
__device__ unsigned short g_xh [MTOK*DMOD], g_xl [MTOK*DMOD];
__device__ unsigned short g_WqTh[DMOD*DMOD], g_WqTl[DMOD*DMOD];
__device__ unsigned short g_WkTh[DH*DMOD],   g_WkTl[DH*DMOD];
__device__ unsigned short g_WvTh[DH*DMOD],   g_WvTl[DH*DMOD];
__device__ unsigned short g_WoTh[DMOD*DMOD], g_WoTl[DMOD*DMOD];
__device__ unsigned short g_Qh [MTOK*DMOD], g_Ql [MTOK*DMOD];
__device__ unsigned short g_Kh [MTOK*DH],   g_Kl [MTOK*DH];
__device__ unsigned short g_Vth[NB*DH*SEQ], g_Vtl[NB*DH*SEQ];
__device__ unsigned short g_AOh[MTOK*DMOD], g_AOl[MTOK*DMOD];

// ---------------- helpers ----------------
__device__ __forceinline__ void mma_bf16(float* c, const u32* a, const u32* b) {
    asm("mma.sync.aligned.m16n8k16.row.col.f32.bf16.bf16.f32 "
        "{%0,%1,%2,%3},{%4,%5,%6,%7},{%8,%9},{%0,%1,%2,%3};"
        : "+f"(c[0]), "+f"(c[1]), "+f"(c[2]), "+f"(c[3])
        : "r"(a[0]), "r"(a[1]), "r"(a[2]), "r"(a[3]), "r"(b[0]), "r"(b[1]));
}

__device__ __forceinline__ u32 packbf(float a, float b) {   // a -> low 16 bits
    bf162 t = __floats2bfloat162_rn(a, b);
    return *reinterpret_cast<u32*>(&t);
}

// ---------------- converters ----------------
// x fp32 -> hi/lo bf16 (elementwise)
__global__ void split_f32(const float* __restrict__ in,
                          unsigned short* __restrict__ h,
                          unsigned short* __restrict__ l, int n4) {
    int i = blockIdx.x * blockDim.x + threadIdx.x;
    if (i >= n4) return;
    float4 v = ((const float4*)in)[i];
    float h0 = __bfloat162float(__float2bfloat16(v.x));
    float h1 = __bfloat162float(__float2bfloat16(v.y));
    float h2 = __bfloat162float(__float2bfloat16(v.z));
    float h3 = __bfloat162float(__float2bfloat16(v.w));
    ((u32*)h)[2*i]   = packbf(h0, h1);
    ((u32*)h)[2*i+1] = packbf(h2, h3);
    ((u32*)l)[2*i]   = packbf(v.x - h0, v.y - h1);
    ((u32*)l)[2*i+1] = packbf(v.z - h2, v.w - h3);
}

// W[K][N] fp32 -> WT[N][K] hi/lo bf16 (tiled transpose + split)
__global__ void wtsplit(const float* __restrict__ W,
                        unsigned short* __restrict__ Th,
                        unsigned short* __restrict__ Tl, int K, int N) {
    __shared__ float t[32][33];
    int nt = blockIdx.x * 32, kt = blockIdx.y * 32;
    int tx = threadIdx.x, ty = threadIdx.y;        // (32, 8)
#pragma unroll
    for (int j = 0; j < 4; j++)
        t[ty + 8*j][tx] = W[(size_t)(kt + ty + 8*j) * N + nt + tx];
    __syncthreads();
#pragma unroll
    for (int j = 0; j < 4; j++) {
        float v = t[tx][ty + 8*j];                  // = W[kt+tx][nt+ty+8j]
        float hv = __bfloat162float(__float2bfloat16(v));
        size_t idx = (size_t)(nt + ty + 8*j) * K + kt + tx;
        ((bf16*)Th)[idx] = __float2bfloat16(hv);
        ((bf16*)Tl)[idx] = __float2bfloat16(v - hv);
    }
}

// ---------------- bf16x3 GEMM via mma.sync ----------------
// C[M,N] = (Ah+Al)[M,K] @ (Bh+Bl)^T  + bias   (B given transposed: [N][K])
// MODE 0: write fp32 Cf.  MODE 1: write hi/lo bf16 (x scale).  MODE 2: V-transposed hi/lo.
#define SASTR 40            // padded smem row stride (bf16 elems) -> conflict-free
template<int MODE>
__global__ __launch_bounds__(256)
void gemm3(const unsigned short* __restrict__ Ah_, const unsigned short* __restrict__ Al_,
           const unsigned short* __restrict__ Bh_, const unsigned short* __restrict__ Bl_,
           const float* __restrict__ bias,
           float* __restrict__ Cf,
           unsigned short* __restrict__ Ch_, unsigned short* __restrict__ Cl_,
           int M, int N, int K, float scale)
{
    __shared__ __align__(16) unsigned short sA[2 * 128 * SASTR];
    __shared__ __align__(16) unsigned short sB[2 * 128 * SASTR];
    const int tid  = threadIdx.x;
    const int warp = tid >> 5, lane = tid & 31;
    const int g = lane >> 2, tig = lane & 3;
    const int wm = warp >> 1, wn = warp & 1;            // 4 x 2 warp grid
    const int m0 = blockIdx.y * 128, n0 = blockIdx.x * 128;

    float acc[2][8][4];
#pragma unroll
    for (int i = 0; i < 2; i++)
#pragma unroll
        for (int j = 0; j < 8; j++)
#pragma unroll
            for (int e = 0; e < 4; e++) acc[i][j][e] = 0.f;

    const int lr = tid >> 1, lc = (tid & 1) * 16;       // loader: row, 16-col half

    for (int kt = 0; kt < K; kt += 32) {
        const size_t aoff = (size_t)(m0 + lr) * K + kt + lc;
        const size_t boff = (size_t)(n0 + lr) * K + kt + lc;
        const int sidx = lr * SASTR + lc;
        *(uint4*)&sA[sidx]          = *(const uint4*)(Ah_ + aoff);
        *(uint4*)&sA[sidx + 8]      = *(const uint4*)(Ah_ + aoff + 8);
        *(uint4*)&sA[5120 + sidx]   = *(const uint4*)(Al_ + aoff);
        *(uint4*)&sA[5120 + sidx+8] = *(const uint4*)(Al_ + aoff + 8);
        *(uint4*)&sB[sidx]          = *(const uint4*)(Bh_ + boff);
        *(uint4*)&sB[sidx + 8]      = *(const uint4*)(Bh_ + boff + 8);
        *(uint4*)&sB[5120 + sidx]   = *(const uint4*)(Bl_ + boff);
        *(uint4*)&sB[5120 + sidx+8] = *(const uint4*)(Bl_ + boff + 8);
        __syncthreads();

#pragma unroll
        for (int s = 0; s < 2; s++) {
            u32 af[2][2][4];
#pragma unroll
            for (int hl = 0; hl < 2; hl++)
#pragma unroll
                for (int mf = 0; mf < 2; mf++) {
                    int base = hl*5120 + (wm*32 + mf*16 + g) * SASTR + s*16 + 2*tig;
                    af[hl][mf][0] = *(const u32*)&sA[base];
                    af[hl][mf][1] = *(const u32*)&sA[base + 8*SASTR];
                    af[hl][mf][2] = *(const u32*)&sA[base + 8];
                    af[hl][mf][3] = *(const u32*)&sA[base + 8*SASTR + 8];
                }
#pragma unroll
            for (int nf = 0; nf < 8; nf++) {
                int bb = (wn*64 + nf*8 + g) * SASTR + s*16 + 2*tig;
                u32 bh[2], bl[2];
                bh[0] = *(const u32*)&sB[bb];
                bh[1] = *(const u32*)&sB[bb + 8];
                bl[0] = *(const u32*)&sB[5120 + bb];
                bl[1] = *(const u32*)&sB[5120 + bb + 8];
#pragma unroll
                for (int mf = 0; mf < 2; mf++) {
                    mma_bf16(acc[mf][nf], af[0][mf], bh);   // Ah*Bh
                    mma_bf16(acc[mf][nf], af[0][mf], bl);   // Ah*Bl
                    mma_bf16(acc[mf][nf], af[1][mf], bh);   // Al*Bh
                }
            }
        }
        __syncthreads();
    }

    // ---- epilogue ----
#pragma unroll
    for (int mf = 0; mf < 2; mf++) {
        int r0 = m0 + wm*32 + mf*16 + g;
#pragma unroll
        for (int nf = 0; nf < 8; nf++) {
            int c = n0 + wn*64 + nf*8 + 2*tig;
            float b0 = bias[c], b1 = bias[c + 1];
            float v0 = acc[mf][nf][0] + b0, v1 = acc[mf][nf][1] + b1;
            float v2 = acc[mf][nf][2] + b0, v3 = acc[mf][nf][3] + b1;
            if (MODE == 0) {
                *(float2*)&Cf[(size_t)r0 * N + c]       = make_float2(v0, v1);
                *(float2*)&Cf[(size_t)(r0 + 8) * N + c] = make_float2(v2, v3);
            } else if (MODE == 1) {
                v0 *= scale; v1 *= scale; v2 *= scale; v3 *= scale;
                float h0 = __bfloat162float(__float2bfloat16(v0));
                float h1 = __bfloat162float(__float2bfloat16(v1));
                float h2 = __bfloat162float(__float2bfloat16(v2));
                float h3 = __bfloat162float(__float2bfloat16(v3));
                *(u32*)&Ch_[(size_t)r0 * N + c]       = packbf(h0, h1);
                *(u32*)&Ch_[(size_t)(r0 + 8) * N + c] = packbf(h2, h3);
                *(u32*)&Cl_[(size_t)r0 * N + c]       = packbf(v0 - h0, v1 - h1);
                *(u32*)&Cl_[(size_t)(r0 + 8) * N + c] = packbf(v2 - h2, v3 - h3);
            } else {  // MODE 2 : V transposed  Vt[b][e=c][s] , b = row>>11
                float vv[4] = {v0, v1, v2, v3};
#pragma unroll
                for (int e = 0; e < 4; e++) {
                    int r = (e < 2) ? r0 : r0 + 8;
                    int cc = c + (e & 1);
                    float v = vv[e];
                    float hv = __bfloat162float(__float2bfloat16(v));
                    size_t idx = ((size_t)(r >> 11) * DH + cc) * SEQ + (r & 2047);
                    ((bf16*)Ch_)[idx] = __float2bfloat16(hv);
                    ((bf16*)Cl_)[idx] = __float2bfloat16(v - hv);
                }
            }
        }
    }
}

// ---------------- flash attention, bf16x3 mma ----------------
// block: 128 thr (4 warps), 64 q-rows for one (b,h). K-tile = 64 keys.
#define KSTR 136            // sK row stride (bf16), rows = keys(64), cols = d(128)
#define VSTR 72             // sV row stride,  rows = e(128),  cols = keys(64)
#define SKELEMS (64 * KSTR)     // 8704
#define SVELEMS (128 * VSTR)    // 9216
#define FLASH_SMEM ((2*SKELEMS + 2*SVELEMS) * 2)   // 71680 B

__global__ __launch_bounds__(128)
void flash_mma(const unsigned short* __restrict__ Qh_, const unsigned short* __restrict__ Ql_,
               const unsigned short* __restrict__ Kh_, const unsigned short* __restrict__ Kl_,
               const unsigned short* __restrict__ Vth_, const unsigned short* __restrict__ Vtl_,
               unsigned short* __restrict__ AOh_, unsigned short* __restrict__ AOl_)
{
    extern __shared__ __align__(16) unsigned short sm[];
    unsigned short* sK0 = sm;
    unsigned short* sK1 = sK0 + SKELEMS;
    unsigned short* sV0 = sK1 + SKELEMS;
    unsigned short* sV1 = sV0 + SVELEMS;

    const int tid = threadIdx.x;
    const int w = tid >> 5, lane = tid & 31;
    const int g = lane >> 2, tig = lane & 3;
    const int b = blockIdx.y >> 4, h = blockIdx.y & 15;
    const int qrow = blockIdx.x * 64 + w * 16 + g;

    // ---- Q fragments resident in registers (hi/lo), Q already scaled ----
    u32 qf[2][8][4];
    {
        size_t qb = (size_t)(b * SEQ + qrow) * DMOD + h * DH;
#pragma unroll
        for (int s = 0; s < 8; s++) {
            int col = s * 16 + 2 * tig;
            qf[0][s][0] = *(const u32*)(Qh_ + qb + col);
            qf[0][s][1] = *(const u32*)(Qh_ + qb + 8ull * DMOD + col);
            qf[0][s][2] = *(const u32*)(Qh_ + qb + col + 8);
            qf[0][s][3] = *(const u32*)(Qh_ + qb + 8ull * DMOD + col + 8);
            qf[1][s][0] = *(const u32*)(Ql_ + qb + col);
            qf[1][s][1] = *(const u32*)(Ql_ + qb + 8ull * DMOD + col);
            qf[1][s][2] = *(const u32*)(Ql_ + qb + col + 8);
            qf[1][s][3] = *(const u32*)(Ql_ + qb + 8ull * DMOD + col + 8);
        }
    }

    float pacc[16][4];
#pragma unroll
    for (int i = 0; i < 16; i++)
#pragma unroll
        for (int e = 0; e < 4; e++) pacc[i][e] = 0.f;
    float m0 = -1e30f, m1 = -1e30f, l0 = 0.f, l1 = 0.f;

    for (int t0 = 0; t0 < SEQ; t0 += 64) {
        // ---- stage K (hi/lo) and Vt (hi/lo) tiles ----
#pragma unroll
        for (int i = tid; i < 1024; i += 128) {
            int r = i >> 4, c = (i & 15) * 8;
            size_t go = (size_t)(b * SEQ + t0 + r) * DH + c;
            *(uint4*)&sK0[r * KSTR + c] = *(const uint4*)(Kh_ + go);
            *(uint4*)&sK1[r * KSTR + c] = *(const uint4*)(Kl_ + go);
        }
#pragma unroll
        for (int i = tid; i < 1024; i += 128) {
            int e = i >> 3, c = (i & 7) * 8;
            size_t go = (size_t)(b * DH + e) * SEQ + t0 + c;
            *(uint4*)&sV0[e * VSTR + c] = *(const uint4*)(Vth_ + go);
            *(uint4*)&sV1[e * VSTR + c] = *(const uint4*)(Vtl_ + go);
        }
        __syncthreads();

        // ---- scores S = Q K^T  (m16 x n64, K=128) ----
        float sa[8][4];
#pragma unroll
        for (int nf = 0; nf < 8; nf++)
#pragma unroll
            for (int e = 0; e < 4; e++) sa[nf][e] = 0.f;

#pragma unroll
        for (int s = 0; s < 8; s++) {
#pragma unroll
            for (int nf = 0; nf < 8; nf++) {
                int bb = (nf * 8 + g) * KSTR + s * 16 + 2 * tig;
                u32 bh[2], bl[2];
                bh[0] = *(const u32*)&sK0[bb];
                bh[1] = *(const u32*)&sK0[bb + 8];
                bl[0] = *(const u32*)&sK1[bb];
                bl[1] = *(const u32*)&sK1[bb + 8];
                mma_bf16(sa[nf], qf[0][s], bh);
                mma_bf16(sa[nf], qf[0][s], bl);
                mma_bf16(sa[nf], qf[1][s], bh);
            }
        }

        // ---- online softmax (thread owns rows g and g+8 of its warp tile) ----
        float mx0 = -1e30f, mx1 = -1e30f;
#pragma unroll
        for (int nf = 0; nf < 8; nf++) {
            mx0 = fmaxf(mx0, fmaxf(sa[nf][0], sa[nf][1]));
            mx1 = fmaxf(mx1, fmaxf(sa[nf][2], sa[nf][3]));
        }
        mx0 = fmaxf(mx0, __shfl_xor_sync(0xffffffffu, mx0, 1));
        mx0 = fmaxf(mx0, __shfl_xor_sync(0xffffffffu, mx0, 2));
        mx1 = fmaxf(mx1, __shfl_xor_sync(0xffffffffu, mx1, 1));
        mx1 = fmaxf(mx1, __shfl_xor_sync(0xffffffffu, mx1, 2));
        float nm0 = fmaxf(m0, mx0), nm1 = fmaxf(m1, mx1);
        float corr0 = __expf(m0 - nm0), corr1 = __expf(m1 - nm1);
        m0 = nm0; m1 = nm1;

        u32 aph[4][4], apl[4][4];          // P fragments (hi / lo), 4 k-slices
        float rs0 = 0.f, rs1 = 0.f;
#pragma unroll
        for (int nf = 0; nf < 8; nf++) {
            float p0 = __expf(sa[nf][0] - nm0);
            float p1 = __expf(sa[nf][1] - nm0);
            float p2 = __expf(sa[nf][2] - nm1);
            float p3 = __expf(sa[nf][3] - nm1);
            rs0 += p0 + p1; rs1 += p2 + p3;
            float h0 = __bfloat162float(__float2bfloat16(p0));
            float h1 = __bfloat162float(__float2bfloat16(p1));
            float h2 = __bfloat162float(__float2bfloat16(p2));
            float h3 = __bfloat162float(__float2bfloat16(p3));
            int ks = nf >> 1, pt = (nf & 1) * 2;
            aph[ks][pt]     = packbf(h0, h1);
            aph[ks][pt + 1] = packbf(h2, h3);
            apl[ks][pt]     = packbf(p0 - h0, p1 - h1);
            apl[ks][pt + 1] = packbf(p2 - h2, p3 - h3);
        }
        rs0 += __shfl_xor_sync(0xffffffffu, rs0, 1);
        rs0 += __shfl_xor_sync(0xffffffffu, rs0, 2);
        rs1 += __shfl_xor_sync(0xffffffffu, rs1, 1);
        rs1 += __shfl_xor_sync(0xffffffffu, rs1, 2);
        l0 = l0 * corr0 + rs0;
        l1 = l1 * corr1 + rs1;
#pragma unroll
        for (int nf = 0; nf < 16; nf++) {
            pacc[nf][0] *= corr0; pacc[nf][1] *= corr0;
            pacc[nf][2] *= corr1; pacc[nf][3] *= corr1;
        }

        // ---- pacc += P V  (m16 x n128, K=64) ----
#pragma unroll
        for (int ks = 0; ks < 4; ks++) {
#pragma unroll
            for (int nf = 0; nf < 16; nf++) {
                int bb = (nf * 8 + g) * VSTR + ks * 16 + 2 * tig;
                u32 bh[2], bl[2];
                bh[0] = *(const u32*)&sV0[bb];
                bh[1] = *(const u32*)&sV0[bb + 8];
                bl[0] = *(const u32*)&sV1[bb];
                bl[1] = *(const u32*)&sV1[bb + 8];
                mma_bf16(pacc[nf], aph[ks], bh);
                mma_bf16(pacc[nf], aph[ks], bl);
                mma_bf16(pacc[nf], apl[ks], bh);
            }
        }
        __syncthreads();
    }

    // ---- epilogue: normalize, split hi/lo, write AO bf16 ----
    float inv0 = 1.f / l0, inv1 = 1.f / l1;
    size_t row0 = (size_t)(b * SEQ + qrow) * DMOD + h * DH;
#pragma unroll
    for (int nf = 0; nf < 16; nf++) {
        int c = nf * 8 + 2 * tig;
        float v0 = pacc[nf][0] * inv0, v1 = pacc[nf][1] * inv0;
        float v2 = pacc[nf][2] * inv1, v3 = pacc[nf][3] * inv1;
        float h0 = __bfloat162float(__float2bfloat16(v0));
        float h1 = __bfloat162float(__float2bfloat16(v1));
        float h2 = __bfloat162float(__float2bfloat16(v2));
        float h3 = __bfloat162float(__float2bfloat16(v3));
        *(u32*)(AOh_ + row0 + c)              = packbf(h0, h1);
        *(u32*)(AOh_ + row0 + 8ull*DMOD + c)  = packbf(h2, h3);
        *(u32*)(AOl_ + row0 + c)              = packbf(v0 - h0, v1 - h1);
        *(u32*)(AOl_ + row0 + 8ull*DMOD + c)  = packbf(v2 - h2, v3 - h3);
    }
}

// ---------------- launch ----------------
extern "C" void kernel_launch(void* const* d_in, const int* in_sizes, int n_in,
                              void* d_out, int out_size)
{
    (void)in_sizes; (void)n_in; (void)out_size;
    const float* x  = (const float*)d_in[0];
    const float* Wq = (const float*)d_in[1];
    const float* bq = (const float*)d_in[2];
    const float* Wk = (const float*)d_in[3];
    const float* bk = (const float*)d_in[4];
    const float* Wv = (const float*)d_in[5];
    const float* bv = (const float*)d_in[6];
    const float* Wo = (const float*)d_in[7];
    const float* bo = (const float*)d_in[8];
    float* out = (float*)d_out;

    void *xh,*xl,*wqh,*wql,*wkh,*wkl,*wvh,*wvl,*woh,*wol;
    void *qh,*ql,*kh,*kl,*vth,*vtl,*aoh,*aol;
    cudaGetSymbolAddress(&xh,  g_xh);   cudaGetSymbolAddress(&xl,  g_xl);
    cudaGetSymbolAddress(&wqh, g_WqTh); cudaGetSymbolAddress(&wql, g_WqTl);
    cudaGetSymbolAddress(&wkh, g_WkTh); cudaGetSymbolAddress(&wkl, g_WkTl);
    cudaGetSymbolAddress(&wvh, g_WvTh); cudaGetSymbolAddress(&wvl, g_WvTl);
    cudaGetSymbolAddress(&woh, g_WoTh); cudaGetSymbolAddress(&wol, g_WoTl);
    cudaGetSymbolAddress(&qh,  g_Qh);   cudaGetSymbolAddress(&ql,  g_Ql);
    cudaGetSymbolAddress(&kh,  g_Kh);   cudaGetSymbolAddress(&kl,  g_Kl);
    cudaGetSymbolAddress(&vth, g_Vth);  cudaGetSymbolAddress(&vtl, g_Vtl);
    cudaGetSymbolAddress(&aoh, g_AOh);  cudaGetSymbolAddress(&aol, g_AOl);

    cudaFuncSetAttribute(flash_mma,
                         cudaFuncAttributeMaxDynamicSharedMemorySize, FLASH_SMEM);

    // 0) convert inputs
    int n4 = MTOK * DMOD / 4;
    split_f32<<<(n4 + 255) / 256, 256>>>(x, (unsigned short*)xh, (unsigned short*)xl, n4);
    wtsplit<<<dim3(DMOD/32, DMOD/32), dim3(32, 8)>>>(Wq, (unsigned short*)wqh, (unsigned short*)wql, DMOD, DMOD);
    wtsplit<<<dim3(DH/32,   DMOD/32), dim3(32, 8)>>>(Wk, (unsigned short*)wkh, (unsigned short*)wkl, DMOD, DH);
    wtsplit<<<dim3(DH/32,   DMOD/32), dim3(32, 8)>>>(Wv, (unsigned short*)wvh, (unsigned short*)wvl, DMOD, DH);
    wtsplit<<<dim3(DMOD/32, DMOD/32), dim3(32, 8)>>>(Wo, (unsigned short*)woh, (unsigned short*)wol, DMOD, DMOD);

    // 1) Q = (x Wq + bq) * scale  -> hi/lo bf16
    gemm3<1><<<dim3(DMOD/128, MTOK/128), 256>>>(
        (unsigned short*)xh, (unsigned short*)xl, (unsigned short*)wqh, (unsigned short*)wql,
        bq, nullptr, (unsigned short*)qh, (unsigned short*)ql, MTOK, DMOD, DMOD, QSCALE);
    // 2) K = x Wk + bk -> hi/lo
    gemm3<1><<<dim3(1, MTOK/128), 256>>>(
        (unsigned short*)xh, (unsigned short*)xl, (unsigned short*)wkh, (unsigned short*)wkl,
        bk, nullptr, (unsigned short*)kh, (unsigned short*)kl, MTOK, DH, DMOD, 1.f);
    // 3) V = x Wv + bv -> transposed hi/lo
    gemm3<2><<<dim3(1, MTOK/128), 256>>>(
        (unsigned short*)xh, (unsigned short*)xl, (unsigned short*)wvh, (unsigned short*)wvl,
        bv, nullptr, (unsigned short*)vth, (unsigned short*)vtl, MTOK, DH, DMOD, 1.f);
    // 4) flash attention -> AO hi/lo
    flash_mma<<<dim3(SEQ/64, NB*NH), 128, FLASH_SMEM>>>(
        (unsigned short*)qh, (unsigned short*)ql, (unsigned short*)kh, (unsigned short*)kl,
        (unsigned short*)vth, (unsigned short*)vtl, (unsigned short*)aoh, (unsigned short*)aol);
    // 5) out = AO Wo + bo (fp32)
    gemm3<0><<<dim3(DMOD/128, MTOK/128), 256>>>(
        (unsigned short*)aoh, (unsigned short*)aol, (unsigned short*)woh, (unsigned short*)wol,
        bo, out, nullptr, nullptr, MTOK, DMOD, DMOD, 1.f);
}